// round 16
// baseline (speedup 1.0000x reference)
#include <cuda_runtime.h>
#include <math.h>

#define TK 16384
#define SS 256

__device__ float g_h  [TK*128];
__device__ float g_ln [TK*128];
__device__ float g_up [TK*512];
__device__ float g_xc [TK*256];
__device__ float g_q  [TK*256];
__device__ float g_k  [TK*256];
__device__ float g_v  [TK*256];
__device__ float g_pre[TK*256];
__device__ float g_ffu[TK*384];
__device__ float g_gate[TK*512];
__device__ float g_ys [TK*128];
__device__ float g_ig [64*4*SS];
__device__ float g_fg [64*4*SS];

__device__ __forceinline__ float siluf(float x){ return x/(1.f+__expf(-x)); }
__device__ __forceinline__ float ftanh(float x){ return 2.f/(1.f+__expf(-2.f*x)) - 1.f; }

__device__ __forceinline__ void f2fma(float2& d, const float2& a, const float2& b){
    asm("fma.rn.f32x2 %0, %1, %2, %0;"
        : "+l"(reinterpret_cast<unsigned long long&>(d))
        : "l"(reinterpret_cast<const unsigned long long&>(a)),
          "l"(reinterpret_cast<const unsigned long long&>(b)));
}

__device__ __forceinline__ unsigned bfpack(float xo, float xe){
    unsigned d;
    asm("cvt.rn.bf16x2.f32 %0, %1, %2;" : "=r"(d) : "f"(xo), "f"(xe));
    return d;
}
__device__ __forceinline__ void bfsplit(float xe, float xo, unsigned& hi, unsigned& lo){
    hi = bfpack(xo, xe);
    float he = __uint_as_float(hi << 16);
    float ho = __uint_as_float(hi & 0xFFFF0000u);
    lo = bfpack(xo - ho, xe - he);
}

__device__ __forceinline__ void mma16(float* d, const unsigned* a, const unsigned* b){
    asm("mma.sync.aligned.m16n8k16.row.col.f32.bf16.bf16.f32 "
        "{%0,%1,%2,%3},{%4,%5,%6,%7},{%8,%9},{%0,%1,%2,%3};"
        : "+f"(d[0]),"+f"(d[1]),"+f"(d[2]),"+f"(d[3])
        : "r"(a[0]),"r"(a[1]),"r"(a[2]),"r"(a[3]), "r"(b[0]),"r"(b[1]));
}

// embed + first LayerNorm fused
__global__ void __launch_bounds__(128) k_embed_ln(const float* __restrict__ x,
                                                  const float* __restrict__ W,
                                                  const float* __restrict__ b,
                                                  const float* __restrict__ lnw){
    __shared__ float ps[4], pq[4];
    int t = blockIdx.x, d = threadIdx.x;
    int lane = d&31, warp = d>>5;
    float h = x[t*3]*W[d] + x[t*3+1]*W[128+d] + x[t*3+2]*W[256+d] + b[d];
    g_h[(long)t*128+d] = h;
    float a1=h, a2=h*h;
    #pragma unroll
    for(int o=16;o;o>>=1){ a1+=__shfl_xor_sync(~0u,a1,o); a2+=__shfl_xor_sync(~0u,a2,o); }
    if(lane==0){ ps[warp]=a1; pq[warp]=a2; }
    __syncthreads();
    float S1 = (ps[0]+ps[1])+(ps[2]+ps[3]);
    float S2 = (pq[0]+pq[1])+(pq[2]+pq[3]);
    float mu = S1*(1.f/128.f);
    float r  = rsqrtf(S2*(1.f/128.f)-mu*mu + 1e-6f);
    g_ln[(long)t*128+d] = (h-mu)*r*lnw[d];
}

// ---------- split-bf16 (bf16x3) tensor GEMM ----------
#define OFF_ALO 1536
#define OFF_BHI 3072
#define OFF_BLO 4160
#define BUFU    5248
#define GB_STRIDE 136
#define GEMM_SMEM ((2*BUFU + 512)*4)
template<int AMODE, bool RESID, bool LNEPI>
__global__ void __launch_bounds__(256,2) k_gemm128(const float* __restrict__ A,
                                                   const float* __restrict__ Bw,
                                                   float* __restrict__ C, int K, int N,
                                                   const float* __restrict__ lnw){
    extern __shared__ unsigned su[];
    float* spart = (float*)(su + 2*BUFU);
    int bm = blockIdx.y<<7, bn = blockIdx.x<<7;
    int tid = threadIdx.x, lane = tid&31, w = tid>>5;
    int wm = (w&3)<<5, wn = (w>>2)<<6;
    int g = lane>>2, t = lane&3;
    float acc[2][8][4];
    #pragma unroll
    for(int i=0;i<2;i++)
        #pragma unroll
        for(int j=0;j<8;j++)
            #pragma unroll
            for(int e=0;e<4;e++) acc[i][j][e]=0.f;
    int ar = tid>>1, ac = (tid&1)<<3;
    int kp = tid>>5, nc = (lane)<<2;
    const float* pA = (AMODE==0) ? A + (long)(bm+ar)*K + ac
                                 : A + (long)(bm+ar)*384 + ac;
    const float* pB0 = Bw + (long)(2*kp)*N + bn + nc;
    const float* pB1 = pB0 + N;
    int idxA = ar*12 + (ac>>1);
    int idxB = kp*GB_STRIDE + nc;
    float avr[8];
    float4 bX, bY;
    auto fetchA = [&](int kofs){
        if(AMODE==0){
            float4 x0 = *(const float4*)(pA + kofs);
            float4 x1 = *(const float4*)(pA + kofs + 4);
            avr[0]=x0.x; avr[1]=x0.y; avr[2]=x0.z; avr[3]=x0.w;
            avr[4]=x1.x; avr[5]=x1.y; avr[6]=x1.z; avr[7]=x1.w;
        } else {
            float4 g0 = *(const float4*)(pA + kofs);
            float4 g1 = *(const float4*)(pA + kofs + 4);
            float4 v0 = *(const float4*)(pA + kofs + 192);
            float4 v1 = *(const float4*)(pA + kofs + 196);
            float gg[8]={g0.x,g0.y,g0.z,g0.w,g1.x,g1.y,g1.z,g1.w};
            float vv[8]={v0.x,v0.y,v0.z,v0.w,v1.x,v1.y,v1.z,v1.w};
            #pragma unroll
            for(int q=0;q<8;q++){
                float xx = gg[q];
                float tv = ftanh(0.7978845608f*(xx+0.044715f*xx*xx*xx));
                avr[q] = 0.5f*xx*(1.f+tv)*vv[q];
            }
        }
    };
    auto stage = [&](unsigned* dst){
        unsigned h,l;
        bfsplit(avr[0],avr[1],h,l); dst[idxA  ]=h; dst[OFF_ALO+idxA  ]=l;
        bfsplit(avr[2],avr[3],h,l); dst[idxA+1]=h; dst[OFF_ALO+idxA+1]=l;
        bfsplit(avr[4],avr[5],h,l); dst[idxA+2]=h; dst[OFF_ALO+idxA+2]=l;
        bfsplit(avr[6],avr[7],h,l); dst[idxA+3]=h; dst[OFF_ALO+idxA+3]=l;
        bfsplit(bX.x,bY.x,h,l); dst[OFF_BHI+idxB  ]=h; dst[OFF_BLO+idxB  ]=l;
        bfsplit(bX.y,bY.y,h,l); dst[OFF_BHI+idxB+1]=h; dst[OFF_BLO+idxB+1]=l;
        bfsplit(bX.z,bY.z,h,l); dst[OFF_BHI+idxB+2]=h; dst[OFF_BLO+idxB+2]=l;
        bfsplit(bX.w,bY.w,h,l); dst[OFF_BHI+idxB+3]=h; dst[OFF_BLO+idxB+3]=l;
    };
    fetchA(0);
    bX = *(const float4*)pB0;
    bY = *(const float4*)pB1;
    stage(su);
    __syncthreads();
    int nk = K>>4;
    for(int kt=0; kt<nk; kt++){
        const unsigned* base = su + (kt&1)*BUFU;
        bool nxt = (kt+1 < nk);
        if(nxt){
            fetchA((kt+1)*16);
            bX = *(const float4*)(pB0 + (long)(kt+1)*16*N);
            bY = *(const float4*)(pB1 + (long)(kt+1)*16*N);
        }
        unsigned ahi[2][4], alo[2][4];
        #pragma unroll
        for(int i=0;i<2;i++){
            const unsigned* Ap = base + (wm+i*16+g)*12 + t;
            ahi[i][0]=Ap[0];      ahi[i][1]=Ap[96];
            ahi[i][2]=Ap[4];      ahi[i][3]=Ap[100];
            const unsigned* Al = Ap + OFF_ALO;
            alo[i][0]=Al[0];      alo[i][1]=Al[96];
            alo[i][2]=Al[4];      alo[i][3]=Al[100];
        }
        #pragma unroll
        for(int j=0;j<8;j++){
            int n0 = wn + j*8;
            const unsigned* Bh = base + OFF_BHI + t*GB_STRIDE + n0 + g;
            const unsigned* Bl = base + OFF_BLO + t*GB_STRIDE + n0 + g;
            unsigned bhi[2] = {Bh[0], Bh[4*GB_STRIDE]};
            unsigned blo[2] = {Bl[0], Bl[4*GB_STRIDE]};
            mma16(acc[0][j], ahi[0], bhi);
            mma16(acc[1][j], ahi[1], bhi);
            mma16(acc[0][j], ahi[0], blo);
            mma16(acc[1][j], ahi[1], blo);
            mma16(acc[0][j], alo[0], bhi);
            mma16(acc[1][j], alo[1], bhi);
        }
        if(nxt) stage(su + ((kt+1)&1)*BUFU);
        __syncthreads();
    }
    #pragma unroll
    for(int i=0;i<2;i++){
        int row = bm + wm + i*16 + g;
        #pragma unroll
        for(int j=0;j<8;j++){
            int col = bn + wn + j*8 + 2*t;
            float2* cp0 = (float2*)(C + (long)row*N + col);
            float2* cp1 = (float2*)(C + (long)(row+8)*N + col);
            if(RESID){
                float2 o0 = *cp0, o1 = *cp1;
                acc[i][j][0]+=o0.x; acc[i][j][1]+=o0.y;
                acc[i][j][2]+=o1.x; acc[i][j][3]+=o1.y;
            }
            *cp0 = make_float2(acc[i][j][0], acc[i][j][1]);
            *cp1 = make_float2(acc[i][j][2], acc[i][j][3]);
        }
    }
    if(LNEPI){
        int wc = w>>2;
        float rs1[4]={0.f,0.f,0.f,0.f}, rs2[4]={0.f,0.f,0.f,0.f};
        #pragma unroll
        for(int i=0;i<2;i++)
            #pragma unroll
            for(int j=0;j<8;j++){
                float e0=acc[i][j][0], e1=acc[i][j][1];
                float e2=acc[i][j][2], e3=acc[i][j][3];
                rs1[i*2  ] += e0+e1; rs2[i*2  ] += e0*e0+e1*e1;
                rs1[i*2+1] += e2+e3; rs2[i*2+1] += e2*e2+e3*e3;
            }
        #pragma unroll
        for(int o=1;o<4;o<<=1)
            #pragma unroll
            for(int q=0;q<4;q++){
                rs1[q]+=__shfl_xor_sync(~0u,rs1[q],o);
                rs2[q]+=__shfl_xor_sync(~0u,rs2[q],o);
            }
        if(t==0){
            #pragma unroll
            for(int q=0;q<4;q++){
                int lr = wm + (q>>1)*16 + g + (q&1)*8;
                spart[lr*4 + wc*2    ] = rs1[q];
                spart[lr*4 + wc*2 + 1] = rs2[q];
            }
        }
        __syncthreads();
        #pragma unroll
        for(int i=0;i<2;i++)
            #pragma unroll
            for(int half=0; half<2; half++){
                int lr = wm + i*16 + g + half*8;
                float S1 = spart[lr*4] + spart[lr*4+2];
                float S2 = spart[lr*4+1] + spart[lr*4+3];
                float mu = S1*(1.f/128.f);
                float r  = rsqrtf(S2*(1.f/128.f)-mu*mu + 1e-6f);
                long row = bm + lr;
                #pragma unroll
                for(int j=0;j<8;j++){
                    int col = wn + j*8 + 2*t;
                    float2 lw = *(const float2*)(lnw + col);
                    float e0 = (acc[i][j][half*2  ]-mu)*r*lw.x;
                    float e1 = (acc[i][j][half*2+1]-mu)*r*lw.y;
                    *(float2*)(g_ln + row*128 + col) = make_float2(e0,e1);
                }
            }
    }
}

// fused causal conv + SiLU + headwise q/k/v
__global__ void __launch_bounds__(256) k_convhead(const float* __restrict__ cw,
                                                  const float* __restrict__ cb,
                                                  const float* __restrict__ Wq,
                                                  const float* __restrict__ Wk,
                                                  const float* __restrict__ Wv){
    __shared__ float sup[19][256];
    __shared__ float sxc[16][256];
    int t0 = blockIdx.x<<4;
    int s0 = t0 & 255;
    int tid = threadIdx.x;
    #pragma unroll
    for(int i=0;i<19;i++){
        int s = s0 - 3 + i;
        sup[i][tid] = (s>=0) ? g_up[(long)(t0-3+i)*512 + tid] : 0.f;
    }
    __syncthreads();
    int c = tid;
    const float* w = cw + c*4;
    float w0=w[0],w1=w[1],w2=w[2],w3=w[3], bb=cb[c];
    #pragma unroll
    for(int t=0;t<16;t++){
        float acc = bb;
        acc = fmaf(sup[t  ][c], w0, acc);
        acc = fmaf(sup[t+1][c], w1, acc);
        acc = fmaf(sup[t+2][c], w2, acc);
        acc = fmaf(sup[t+3][c], w3, acc);
        float xcv = siluf(acc);
        sxc[t][c] = xcv;
        g_xc[(long)(t0+t)*256 + c] = xcv;
    }
    __syncthreads();
    int nb = c>>2, l = c&3;
    float wq[4], wk[4], wv[4];
    #pragma unroll
    for(int k=0;k<4;k++){
        wq[k]=Wq[nb*16+k*4+l]; wk[k]=Wk[nb*16+k*4+l]; wv[k]=Wv[nb*16+k*4+l];
    }
    #pragma unroll
    for(int t=0;t<16;t++){
        float aq=0.f, ak=0.f, av=0.f;
        #pragma unroll
        for(int k=0;k<4;k++){
            float xv = sxc[t][nb*4+k];
            float mv = sup[t+3][nb*4+k];
            aq=fmaf(xv,wq[k],aq); ak=fmaf(xv,wk[k],ak); av=fmaf(mv,wv[k],av);
        }
        g_q[(long)(t0+t)*256+c]=aq;
        g_k[(long)(t0+t)*256+c]=ak;
        g_v[(long)(t0+t)*256+c]=av;
    }
}

// gate projections: 2 tokens per warp, shared weight fetch
__global__ void __launch_bounds__(256) k_gatesproj(const float* __restrict__ Wig,
                                                   const float* __restrict__ big,
                                                   const float* __restrict__ Wfg,
                                                   const float* __restrict__ bfg){
    int warp = threadIdx.x>>5, lane = threadIdx.x&31;
    int t0 = blockIdx.x*16 + warp*2;
    const float* qp0 = g_q + (long)t0*256;
    const float* kp0 = g_k + (long)t0*256;
    const float* vp0 = g_v + (long)t0*256;
    float vA[24], vB[24];
    #pragma unroll
    for(int i=0;i<8;i++){ vA[i]    = qp0[lane+i*32]; vB[i]    = qp0[256+lane+i*32]; }
    #pragma unroll
    for(int i=0;i<8;i++){ vA[8+i]  = kp0[lane+i*32]; vB[8+i]  = kp0[256+lane+i*32]; }
    #pragma unroll
    for(int i=0;i<8;i++){ vA[16+i] = vp0[lane+i*32]; vB[16+i] = vp0[256+lane+i*32]; }
    float iA0=0,iA1=0,iA2=0,iA3=0, fA0=0,fA1=0,fA2=0,fA3=0;
    float iB0=0,iB1=0,iB2=0,iB3=0, fB0=0,fB1=0,fB2=0,fB3=0;
    #pragma unroll
    for(int i=0;i<24;i++){
        int c = i*32 + lane;
        float4 wi = *(const float4*)(Wig + c*4);
        float4 wf = *(const float4*)(Wfg + c*4);
        float a = vA[i], b = vB[i];
        iA0=fmaf(a,wi.x,iA0); iA1=fmaf(a,wi.y,iA1); iA2=fmaf(a,wi.z,iA2); iA3=fmaf(a,wi.w,iA3);
        fA0=fmaf(a,wf.x,fA0); fA1=fmaf(a,wf.y,fA1); fA2=fmaf(a,wf.z,fA2); fA3=fmaf(a,wf.w,fA3);
        iB0=fmaf(b,wi.x,iB0); iB1=fmaf(b,wi.y,iB1); iB2=fmaf(b,wi.z,iB2); iB3=fmaf(b,wi.w,iB3);
        fB0=fmaf(b,wf.x,fB0); fB1=fmaf(b,wf.y,fB1); fB2=fmaf(b,wf.z,fB2); fB3=fmaf(b,wf.w,fB3);
    }
    #pragma unroll
    for(int o=16;o;o>>=1){
        iA0+=__shfl_xor_sync(~0u,iA0,o); iA1+=__shfl_xor_sync(~0u,iA1,o);
        iA2+=__shfl_xor_sync(~0u,iA2,o); iA3+=__shfl_xor_sync(~0u,iA3,o);
        fA0+=__shfl_xor_sync(~0u,fA0,o); fA1+=__shfl_xor_sync(~0u,fA1,o);
        fA2+=__shfl_xor_sync(~0u,fA2,o); fA3+=__shfl_xor_sync(~0u,fA3,o);
        iB0+=__shfl_xor_sync(~0u,iB0,o); iB1+=__shfl_xor_sync(~0u,iB1,o);
        iB2+=__shfl_xor_sync(~0u,iB2,o); iB3+=__shfl_xor_sync(~0u,iB3,o);
        fB0+=__shfl_xor_sync(~0u,fB0,o); fB1+=__shfl_xor_sync(~0u,fB1,o);
        fB2+=__shfl_xor_sync(~0u,fB2,o); fB3+=__shfl_xor_sync(~0u,fB3,o);
    }
    if(lane==0){
        int b0 = t0>>8, s0_ = t0&255;
        int base = b0*1024 + s0_;
        g_ig[base     ] = iA0 + big[0];
        g_ig[base+256 ] = iA1 + big[1];
        g_ig[base+512 ] = iA2 + big[2];
        g_ig[base+768 ] = iA3 + big[3];
        g_fg[base     ] = fA0 + bfg[0];
        g_fg[base+256 ] = fA1 + bfg[1];
        g_fg[base+512 ] = fA2 + bfg[2];
        g_fg[base+768 ] = fA3 + bfg[3];
        int t1 = t0+1;
        int b1 = t1>>8, s1_ = t1&255;
        int base1 = b1*1024 + s1_;
        g_ig[base1     ] = iB0 + big[0];
        g_ig[base1+256 ] = iB1 + big[1];
        g_ig[base1+512 ] = iB2 + big[2];
        g_ig[base1+768 ] = iB3 + big[3];
        g_fg[base1     ] = fB0 + bfg[0];
        g_fg[base1+256 ] = fB1 + bfg[1];
        g_fg[base1+512 ] = fB2 + bfg[2];
        g_fg[base1+768 ] = fB3 + bfg[3];
    }
}

// attention, 512 threads (2 threads per row, 32 dims each) + gate-scan + fused epilogue
#define ATTN_SMEM ((256*64*2 + 256*4)*4)
__global__ void __launch_bounds__(512,1) k_attn(const float* __restrict__ gnw,
                                                const float* __restrict__ skipw){
    extern __shared__ float sm[];
    float2* ks2 = (float2*)sm;
    float2* vs2 = (float2*)(sm + 16384);
    float*  scs = sm + 32768;
    float*  sig = sm + 33024;
    float*  smd = sm + 33280;
    float*  sfg = sm + 33536;
    int b = blockIdx.x>>2, hd = blockIdx.x&3;
    int tid = threadIdx.x;
    for(int i=tid; i<256*16; i+=512){
        int r = i>>4, c = i&15;
        ((float4*)ks2)[i] = *(const float4*)(g_k + (long)(b*256+r)*256 + hd*64 + c*4);
        ((float4*)vs2)[i] = *(const float4*)(g_v + (long)(b*256+r)*256 + hd*64 + c*4);
    }
    if(tid < 256){
        int base = b*1024 + hd*256;
        sig[tid] = g_ig[base+tid];
        sfg[tid] = g_fg[base+tid];
    }
    __syncthreads();
    if(tid < 32){
        int lane = tid;
        float carry = 0.f, cpm = -1e30f;
        for(int ch=0; ch<8; ch++){
            int s = ch*32 + lane;
            float f = sfg[s];
            float lf = (f >= 0.f) ? -log1pf(__expf(-f)) : f - log1pf(__expf(f));
            float sc = lf;
            #pragma unroll
            for(int o=1;o<32;o<<=1){ float v=__shfl_up_sync(~0u,sc,o); if(lane>=o) sc+=v; }
            float cs = carry + sc;
            float e = sig[s] - cs;
            float pm = e;
            #pragma unroll
            for(int o=1;o<32;o<<=1){ float v=__shfl_up_sync(~0u,pm,o); if(lane>=o) pm=fmaxf(pm,v); }
            pm = fmaxf(pm, cpm);
            scs[s] = cs;
            smd[s] = cs + pm;
            carry += __shfl_sync(~0u, sc, 31);
            cpm = fmaxf(cpm, __shfl_sync(~0u, pm, 31));
        }
    }
    __syncthreads();
    int w = tid>>5, lane = tid&31;
    // SMSP-balanced row-block map: columns of {0,7,8,15}{1,6,9,14}{2,5,10,13}{3,4,11,12}
    int jj = w>>2, ss = w&3;
    int rb = (jj==0) ? ss : (jj==1) ? 7-ss : (jj==2) ? 8+ss : 15-ss;
    int row = rb*16 + (lane>>1);
    int half = lane&1;                 // 0: dims 0-31, 1: dims 32-63
    float2 qv[16];
    #pragma unroll
    for(int d=0;d<16;d++)
        qv[d] = *(const float2*)(g_q + (long)(b*256+row)*256 + hd*64 + half*32 + d*2);
    float2 acc[16];
    #pragma unroll
    for(int d=0;d<16;d++) acc[d] = make_float2(0.f,0.f);
    float ssum = 0.f;
    float csi = scs[row], mdi = smd[row];
    int jmax = (rb+1)<<4;
    for(int j=0;j<jmax;j++){
        const float4* kr4 = (const float4*)(ks2 + j*32 + half*16);
        float2 d0 = make_float2(0.f,0.f), d1 = d0, d2 = d0, d3 = d0;
        #pragma unroll
        for(int i=0;i<8;i+=2){
            float4 k0 = kr4[i], k1 = kr4[i+1];
            f2fma(d0, qv[2*i  ], make_float2(k0.x,k0.y));
            f2fma(d1, qv[2*i+1], make_float2(k0.z,k0.w));
            f2fma(d2, qv[2*i+2], make_float2(k1.x,k1.y));
            f2fma(d3, qv[2*i+3], make_float2(k1.z,k1.w));
        }
        float dot = (d0.x+d0.y)+(d1.x+d1.y)+((d2.x+d2.y)+(d3.x+d3.y));
        dot += __shfl_xor_sync(~0u, dot, 1);
        float wv = 0.f;
        if (j <= row){
            wv = 0.125f * dot * __expf(csi - scs[j] + sig[j] - mdi);
            ssum += wv;
        }
        float2 w2 = make_float2(wv, wv);
        const float4* vr4 = (const float4*)(vs2 + j*32 + half*16);
        #pragma unroll
        for(int i=0;i<8;i++){
            float4 vvq = vr4[i];
            f2fma(acc[2*i  ], w2, make_float2(vvq.x,vvq.y));
            f2fma(acc[2*i+1], w2, make_float2(vvq.z,vvq.w));
        }
    }
    float inv = 1.f/(fmaxf(fabsf(ssum), __expf(-mdi)) + 1e-6f);
    float o32[32];
    float s1 = 0.f, s2 = 0.f;
    #pragma unroll
    for(int d=0;d<16;d++){
        float e0 = acc[d].x*inv, e1 = acc[d].y*inv;
        o32[2*d]=e0; o32[2*d+1]=e1;
        s1 += e0+e1; s2 += e0*e0+e1*e1;
    }
    s1 += __shfl_xor_sync(~0u, s1, 1);
    s2 += __shfl_xor_sync(~0u, s2, 1);
    float mu = s1*(1.f/64.f);
    float r  = rsqrtf(s2*(1.f/64.f)-mu*mu + 1e-6f);
    long tglob = (long)(b*256+row);
    const float2* zp  = (const float2*)(g_up + tglob*512 + 256 + hd*64 + half*32);
    const float2* xcp = (const float2*)(g_xc + tglob*256 + hd*64 + half*32);
    const float2* gw  = (const float2*)(gnw + hd*64 + half*32);
    const float2* sw  = (const float2*)(skipw + hd*64 + half*32);
    float2* outp = (float2*)(g_pre + tglob*256 + hd*64 + half*32);
    #pragma unroll
    for(int d=0;d<16;d++){
        float2 z2 = zp[d], xc2 = xcp[d], g2 = gw[d], k2 = sw[d];
        float2 o;
        o.x = ((o32[2*d  ]-mu)*r*g2.x + k2.x*xc2.x) * siluf(z2.x);
        o.y = ((o32[2*d+1]-mu)*r*g2.y + k2.y*xc2.y) * siluf(z2.y);
        outp[d] = o;
    }
}

// fused sLSTM conv + gate-input projections. block = 64 tokens, 512 threads
#define GS_SMEM ((67*128 + 64*128)*4)
__global__ void __launch_bounds__(512) k_gatein_s(const float* __restrict__ cw,
                                                  const float* __restrict__ cb,
                                                  const float* __restrict__ Wg,
                                                  const float* __restrict__ bg){
    extern __shared__ float gs[];
    float* sln = gs;
    float* sxc = gs + 67*128;
    int tid = threadIdx.x;
    int t0 = blockIdx.x*64;
    int s0 = t0 & 255;
    for(int i=tid; i<67*128; i+=512){
        int rr2 = i>>7, cc2 = i&127;
        int s = s0 - 3 + rr2;
        sln[i] = (s>=0) ? g_ln[(long)(t0-3+rr2)*128 + cc2] : 0.f;
    }
    int n = tid>>7, rr = tid&127, l = rr>>2, g = rr&3;
    int gn = g*4+n;
    float wreg[32];
    #pragma unroll
    for(int k=0;k<32;k++) wreg[k] = Wg[gn*1024 + k*32 + l];
    float breg = bg[g*128 + n*32 + l];
    int src = (g>=2);
    __syncthreads();
    {
        int c = tid & 127;
        int tb = tid >> 7;
        float w0=cw[c*4],w1=cw[c*4+1],w2=cw[c*4+2],w3=cw[c*4+3], bb=cb[c];
        #pragma unroll
        for(int p=0;p<16;p++){
            int ti = tb*16 + p;
            float a2 = bb;
            a2 = fmaf(sln[(ti  )*128+c], w0, a2);
            a2 = fmaf(sln[(ti+1)*128+c], w1, a2);
            a2 = fmaf(sln[(ti+2)*128+c], w2, a2);
            a2 = fmaf(sln[(ti+3)*128+c], w3, a2);
            sxc[ti*128+c] = siluf(a2);
        }
    }
    __syncthreads();
    for(int ti=0; ti<64; ti++){
        const float* in = src ? &sln[(ti+3)*128 + n*32] : &sxc[ti*128 + n*32];
        float acc = breg;
        #pragma unroll
        for(int k=0;k<32;k++) acc = fmaf(in[k], wreg[k], acc);
        int t = t0 + ti;
        int b = t>>8, s = t&255;
        g_gate[(long)((s*64+b)*4+n)*128 + l*4 + g] = acc;
    }
}

// sLSTM recurrence: one warp per (b, head)
__global__ void __launch_bounds__(128) k_scan(const float* __restrict__ R){
    int warp = threadIdx.x>>5, l = threadIdx.x&31;
    int p = blockIdx.x*4 + warp;
    int b = p>>2, n = p&3;
    float Rr[4][32];
    #pragma unroll
    for(int g=0;g<4;g++)
        #pragma unroll
        for(int k=0;k<32;k++) Rr[g][k] = R[((g*4+n)*32+k)*32 + l];
    const float4* gp = (const float4*)g_gate;
    long base4 = (b*4+n)*32 + l;
    const long st4 = 64*4*32;
    float c=0.f, nst=0.f, m=0.f, hval=0.f;
    float* yout = g_ys + (long)b*256*128 + n*32 + l;
    float4 gv = gp[base4];
    for(int s=0;s<256;s++){
        float4 gnx = (s<255) ? gp[base4 + (long)(s+1)*st4] : gv;
        float a0=0.f,a1=0.f,b0=0.f,b1=0.f,c0=0.f,c1=0.f,d0=0.f,d1=0.f;
        #pragma unroll
        for(int k=0;k<32;k+=2){
            float h0 = __shfl_sync(~0u,hval,k);
            float h1 = __shfl_sync(~0u,hval,k+1);
            a0 = fmaf(h0, Rr[0][k], a0); a1 = fmaf(h1, Rr[0][k+1], a1);
            b0 = fmaf(h0, Rr[1][k], b0); b1 = fmaf(h1, Rr[1][k+1], b1);
            c0 = fmaf(h0, Rr[2][k], c0); c1 = fmaf(h1, Rr[2][k+1], c1);
            d0 = fmaf(h0, Rr[3][k], d0); d1 = fmaf(h1, Rr[3][k+1], d1);
        }
        float ir = gv.x + (a0+a1), fr = gv.y + (b0+b1);
        float zr = gv.z + (c0+c1), orr = gv.w + (d0+d1);
        float mn = fmaxf(fr + m, ir);
        float ii = __expf(ir - mn);
        float ff = __expf(fr + m - mn);
        float zt = ftanh(zr);
        float o  = 1.f/(1.f+__expf(-orr));
        c   = ff*c + ii*zt;
        nst = ff*nst + ii;
        hval = __fdividef(o*c, nst + 1e-8f);
        m = mn;
        yout[(long)s*128] = hval;
        gv = gnx;
    }
}

// fused sLSTM head-norm + residual add + row LayerNorm
__global__ void __launch_bounds__(128) k_epis_ln(const float* __restrict__ gnw,
                                                 const float* __restrict__ lnw){
    __shared__ float ps[4], pq[4];
    int t = blockIdx.x, c = threadIdx.x;
    int lane = c&31, warp = c>>5;
    float x = g_ys[(long)t*128+c];
    float s1=x, s2=x*x;
    #pragma unroll
    for(int o=16;o;o>>=1){ s1+=__shfl_xor_sync(~0u,s1,o); s2+=__shfl_xor_sync(~0u,s2,o); }
    float mu = s1*(1.f/32.f);
    float r  = rsqrtf(s2*(1.f/32.f)-mu*mu + 1e-6f);
    float hn = g_h[(long)t*128+c] + (x-mu)*r*gnw[c];
    g_h[(long)t*128+c] = hn;
    float a1=hn, a2=hn*hn;
    #pragma unroll
    for(int o=16;o;o>>=1){ a1+=__shfl_xor_sync(~0u,a1,o); a2+=__shfl_xor_sync(~0u,a2,o); }
    if(lane==0){ ps[warp]=a1; pq[warp]=a2; }
    __syncthreads();
    float S1 = (ps[0]+ps[1])+(ps[2]+ps[3]);
    float S2 = (pq[0]+pq[1])+(pq[2]+pq[3]);
    float mu2 = S1*(1.f/128.f);
    float r2  = rsqrtf(S2*(1.f/128.f)-mu2*mu2 + 1e-6f);
    g_ln[(long)t*128+c] = (hn-mu2)*r2*lnw[c];
}

__global__ void k_out(const float* __restrict__ Wout, const float* __restrict__ bout,
                      float* __restrict__ out){
    __shared__ float sm[3][4];
    int b = blockIdx.x, d = threadIdx.x;
    float v = g_ln[(long)(b*256+255)*128 + d];
    #pragma unroll
    for(int o=0;o<3;o++){
        float p = v*Wout[d*3+o];
        #pragma unroll
        for(int off=16;off;off>>=1) p += __shfl_xor_sync(~0u,p,off);
        if((d&31)==0) sm[o][d>>5]=p;
    }
    __syncthreads();
    if(d<3) out[b*3+d] = sm[d][0]+sm[d][1]+sm[d][2]+sm[d][3] + bout[d];
}

extern "C" void kernel_launch(void* const* d_in, const int* in_sizes, int n_in,
                              void* d_out, int out_size){
    const float* x      = (const float*)d_in[0];
    const float* W_emb  = (const float*)d_in[1];
    const float* b_emb  = (const float*)d_in[2];
    const float* m_ln_w = (const float*)d_in[3];
    const float* m_Wup  = (const float*)d_in[4];
    const float* m_cw   = (const float*)d_in[5];
    const float* m_cb   = (const float*)d_in[6];
    const float* m_Wq   = (const float*)d_in[7];
    const float* m_Wk   = (const float*)d_in[8];
    const float* m_Wv   = (const float*)d_in[9];
    const float* m_Wig  = (const float*)d_in[10];
    const float* m_big  = (const float*)d_in[11];
    const float* m_Wfg  = (const float*)d_in[12];
    const float* m_bfg  = (const float*)d_in[13];
    const float* m_gn_w = (const float*)d_in[14];
    const float* m_skip = (const float*)d_in[15];
    const float* m_Wdown= (const float*)d_in[16];
    const float* s_ln_w = (const float*)d_in[17];
    const float* s_cw   = (const float*)d_in[18];
    const float* s_cb   = (const float*)d_in[19];
    const float* s_Wg   = (const float*)d_in[20];
    const float* s_bg   = (const float*)d_in[21];
    const float* s_R    = (const float*)d_in[22];
    const float* s_gn_w = (const float*)d_in[23];
    const float* s_ln2_w= (const float*)d_in[24];
    const float* s_Wfu  = (const float*)d_in[25];
    const float* s_Wfd  = (const float*)d_in[26];
    const float* postw  = (const float*)d_in[27];
    const float* W_out  = (const float*)d_in[28];
    const float* b_out  = (const float*)d_in[29];

    cudaFuncSetAttribute(k_attn, cudaFuncAttributeMaxDynamicSharedMemorySize, ATTN_SMEM);
    cudaFuncSetAttribute(k_gatein_s, cudaFuncAttributeMaxDynamicSharedMemorySize, GS_SMEM);
    cudaFuncSetAttribute(k_gemm128<0,false,false>, cudaFuncAttributeMaxDynamicSharedMemorySize, GEMM_SMEM);
    cudaFuncSetAttribute(k_gemm128<0,true,true>,   cudaFuncAttributeMaxDynamicSharedMemorySize, GEMM_SMEM);
    cudaFuncSetAttribute(k_gemm128<1,true,true>,   cudaFuncAttributeMaxDynamicSharedMemorySize, GEMM_SMEM);

    float *hbuf, *lnb, *upb, *preb, *ffub;
    cudaGetSymbolAddress((void**)&hbuf, g_h);
    cudaGetSymbolAddress((void**)&lnb,  g_ln);
    cudaGetSymbolAddress((void**)&upb,  g_up);
    cudaGetSymbolAddress((void**)&preb, g_pre);
    cudaGetSymbolAddress((void**)&ffub, g_ffu);

    const float* nextw[6] = { s_ln_w, m_ln_w + 128, s_ln_w + 128,
                              m_ln_w + 2*128, m_ln_w + 3*128, postw };

    k_embed_ln<<<TK,128>>>(x, W_emb, b_emb, m_ln_w);

    const char* bt = "msmsmm";
    int mi=0, si=0;
    for(int bi=0; bi<6; bi++){
        if(bt[bi]=='m'){
            { dim3 g2(4, 128);
              k_gemm128<0,false,false><<<g2,256,GEMM_SMEM>>>(lnb, m_Wup + (long)mi*128*512, upb, 128, 512, nullptr); }
            k_convhead<<<TK/16,256>>>(m_cw + mi*1024, m_cb + mi*256,
                                      m_Wq + mi*1024, m_Wk + mi*1024, m_Wv + mi*1024);
            k_gatesproj<<<TK/16,256>>>(m_Wig + mi*3072, m_big + mi*4, m_Wfg + mi*3072, m_bfg + mi*4);
            k_attn<<<256,512,ATTN_SMEM>>>(m_gn_w + mi*256, m_skip + mi*256);
            { dim3 g2(1, 128);
              k_gemm128<0,true,true><<<g2,256,GEMM_SMEM>>>(preb, m_Wdown + (long)mi*256*128, hbuf, 256, 128, nextw[bi]); }
            mi++;
        } else {
            k_gatein_s<<<256,512,GS_SMEM>>>(s_cw + si*512, s_cb + si*128,
                                            s_Wg + si*16384, s_bg + si*512);
            k_scan<<<64,128>>>(s_R + si*16384);
            k_epis_ln<<<TK,128>>>(s_gn_w + si*128, s_ln2_w + si*128);
            { dim3 g2(3, 128);
              k_gemm128<0,false,false><<<g2,256,GEMM_SMEM>>>(lnb, s_Wfu + (long)si*128*384, ffub, 128, 384, nullptr); }
            { dim3 g2(1, 128);
              k_gemm128<1,true,true><<<g2,256,GEMM_SMEM>>>(ffub, s_Wfd + (long)si*192*128, hbuf, 192, 128, nextw[bi]); }
            si++;
        }
    }
    k_out<<<64,128>>>(W_out, b_out, (float*)d_out);
}

// round 17
// speedup vs baseline: 1.1973x; 1.1973x over previous
#include <cuda_runtime.h>
#include <math.h>

#define TK 16384
#define SS 256

__device__ float g_h  [TK*128];
__device__ float g_ln [TK*128];
__device__ float g_up [TK*512];
__device__ float g_xc [TK*256];
__device__ float g_q  [TK*256];
__device__ float g_k  [TK*256];
__device__ float g_v  [TK*256];
__device__ float g_pre[TK*256];
__device__ float g_ffu[TK*384];
__device__ float g_gate[TK*512];
__device__ float g_ys [TK*128];
__device__ float g_ig [64*4*SS];
__device__ float g_fg [64*4*SS];

__device__ __forceinline__ float siluf(float x){ return x/(1.f+__expf(-x)); }
__device__ __forceinline__ float ftanh(float x){ return 2.f/(1.f+__expf(-2.f*x)) - 1.f; }

__device__ __forceinline__ void f2fma(float2& d, const float2& a, const float2& b){
    asm("fma.rn.f32x2 %0, %1, %2, %0;"
        : "+l"(reinterpret_cast<unsigned long long&>(d))
        : "l"(reinterpret_cast<const unsigned long long&>(a)),
          "l"(reinterpret_cast<const unsigned long long&>(b)));
}

__device__ __forceinline__ unsigned bfpack(float xo, float xe){
    unsigned d;
    asm("cvt.rn.bf16x2.f32 %0, %1, %2;" : "=r"(d) : "f"(xo), "f"(xe));
    return d;
}
__device__ __forceinline__ void bfsplit(float xe, float xo, unsigned& hi, unsigned& lo){
    hi = bfpack(xo, xe);
    float he = __uint_as_float(hi << 16);
    float ho = __uint_as_float(hi & 0xFFFF0000u);
    lo = bfpack(xo - ho, xe - he);
}

__device__ __forceinline__ void mma16(float* d, const unsigned* a, const unsigned* b){
    asm("mma.sync.aligned.m16n8k16.row.col.f32.bf16.bf16.f32 "
        "{%0,%1,%2,%3},{%4,%5,%6,%7},{%8,%9},{%0,%1,%2,%3};"
        : "+f"(d[0]),"+f"(d[1]),"+f"(d[2]),"+f"(d[3])
        : "r"(a[0]),"r"(a[1]),"r"(a[2]),"r"(a[3]), "r"(b[0]),"r"(b[1]));
}

// embed + first LayerNorm fused
__global__ void __launch_bounds__(128) k_embed_ln(const float* __restrict__ x,
                                                  const float* __restrict__ W,
                                                  const float* __restrict__ b,
                                                  const float* __restrict__ lnw){
    __shared__ float ps[4], pq[4];
    int t = blockIdx.x, d = threadIdx.x;
    int lane = d&31, warp = d>>5;
    float h = x[t*3]*W[d] + x[t*3+1]*W[128+d] + x[t*3+2]*W[256+d] + b[d];
    g_h[(long)t*128+d] = h;
    float a1=h, a2=h*h;
    #pragma unroll
    for(int o=16;o;o>>=1){ a1+=__shfl_xor_sync(~0u,a1,o); a2+=__shfl_xor_sync(~0u,a2,o); }
    if(lane==0){ ps[warp]=a1; pq[warp]=a2; }
    __syncthreads();
    float S1 = (ps[0]+ps[1])+(ps[2]+ps[3]);
    float S2 = (pq[0]+pq[1])+(pq[2]+pq[3]);
    float mu = S1*(1.f/128.f);
    float r  = rsqrtf(S2*(1.f/128.f)-mu*mu + 1e-6f);
    g_ln[(long)t*128+d] = (h-mu)*r*lnw[d];
}

// ---------- split-bf16 (bf16x3) tensor GEMM ----------
#define OFF_ALO 1536
#define OFF_BHI 3072
#define OFF_BLO 4160
#define BUFU    5248
#define GB_STRIDE 136
#define GEMM_SMEM ((2*BUFU + 512)*4)
template<int AMODE, bool RESID, bool LNEPI>
__global__ void __launch_bounds__(256,2) k_gemm128(const float* __restrict__ A,
                                                   const float* __restrict__ Bw,
                                                   float* __restrict__ C, int K, int N,
                                                   const float* __restrict__ lnw){
    extern __shared__ unsigned su[];
    float* spart = (float*)(su + 2*BUFU);
    int bm = blockIdx.y<<7, bn = blockIdx.x<<7;
    int tid = threadIdx.x, lane = tid&31, w = tid>>5;
    int wm = (w&3)<<5, wn = (w>>2)<<6;
    int g = lane>>2, t = lane&3;
    float acc[2][8][4];
    #pragma unroll
    for(int i=0;i<2;i++)
        #pragma unroll
        for(int j=0;j<8;j++)
            #pragma unroll
            for(int e=0;e<4;e++) acc[i][j][e]=0.f;
    int ar = tid>>1, ac = (tid&1)<<3;
    int kp = tid>>5, nc = (lane)<<2;
    const float* pA = (AMODE==0) ? A + (long)(bm+ar)*K + ac
                                 : A + (long)(bm+ar)*384 + ac;
    const float* pB0 = Bw + (long)(2*kp)*N + bn + nc;
    const float* pB1 = pB0 + N;
    int idxA = ar*12 + (ac>>1);
    int idxB = kp*GB_STRIDE + nc;
    float avr[8];
    float4 bX, bY;
    auto fetchA = [&](int kofs){
        if(AMODE==0){
            float4 x0 = *(const float4*)(pA + kofs);
            float4 x1 = *(const float4*)(pA + kofs + 4);
            avr[0]=x0.x; avr[1]=x0.y; avr[2]=x0.z; avr[3]=x0.w;
            avr[4]=x1.x; avr[5]=x1.y; avr[6]=x1.z; avr[7]=x1.w;
        } else {
            float4 g0 = *(const float4*)(pA + kofs);
            float4 g1 = *(const float4*)(pA + kofs + 4);
            float4 v0 = *(const float4*)(pA + kofs + 192);
            float4 v1 = *(const float4*)(pA + kofs + 196);
            float gg[8]={g0.x,g0.y,g0.z,g0.w,g1.x,g1.y,g1.z,g1.w};
            float vv[8]={v0.x,v0.y,v0.z,v0.w,v1.x,v1.y,v1.z,v1.w};
            #pragma unroll
            for(int q=0;q<8;q++){
                float xx = gg[q];
                float tv = ftanh(0.7978845608f*(xx+0.044715f*xx*xx*xx));
                avr[q] = 0.5f*xx*(1.f+tv)*vv[q];
            }
        }
    };
    auto stage = [&](unsigned* dst){
        unsigned h,l;
        bfsplit(avr[0],avr[1],h,l); dst[idxA  ]=h; dst[OFF_ALO+idxA  ]=l;
        bfsplit(avr[2],avr[3],h,l); dst[idxA+1]=h; dst[OFF_ALO+idxA+1]=l;
        bfsplit(avr[4],avr[5],h,l); dst[idxA+2]=h; dst[OFF_ALO+idxA+2]=l;
        bfsplit(avr[6],avr[7],h,l); dst[idxA+3]=h; dst[OFF_ALO+idxA+3]=l;
        bfsplit(bX.x,bY.x,h,l); dst[OFF_BHI+idxB  ]=h; dst[OFF_BLO+idxB  ]=l;
        bfsplit(bX.y,bY.y,h,l); dst[OFF_BHI+idxB+1]=h; dst[OFF_BLO+idxB+1]=l;
        bfsplit(bX.z,bY.z,h,l); dst[OFF_BHI+idxB+2]=h; dst[OFF_BLO+idxB+2]=l;
        bfsplit(bX.w,bY.w,h,l); dst[OFF_BHI+idxB+3]=h; dst[OFF_BLO+idxB+3]=l;
    };
    fetchA(0);
    bX = *(const float4*)pB0;
    bY = *(const float4*)pB1;
    stage(su);
    __syncthreads();
    int nk = K>>4;
    for(int kt=0; kt<nk; kt++){
        const unsigned* base = su + (kt&1)*BUFU;
        bool nxt = (kt+1 < nk);
        if(nxt){
            fetchA((kt+1)*16);
            bX = *(const float4*)(pB0 + (long)(kt+1)*16*N);
            bY = *(const float4*)(pB1 + (long)(kt+1)*16*N);
        }
        unsigned ahi[2][4], alo[2][4];
        #pragma unroll
        for(int i=0;i<2;i++){
            const unsigned* Ap = base + (wm+i*16+g)*12 + t;
            ahi[i][0]=Ap[0];      ahi[i][1]=Ap[96];
            ahi[i][2]=Ap[4];      ahi[i][3]=Ap[100];
            const unsigned* Al = Ap + OFF_ALO;
            alo[i][0]=Al[0];      alo[i][1]=Al[96];
            alo[i][2]=Al[4];      alo[i][3]=Al[100];
        }
        #pragma unroll
        for(int j=0;j<8;j++){
            int n0 = wn + j*8;
            const unsigned* Bh = base + OFF_BHI + t*GB_STRIDE + n0 + g;
            const unsigned* Bl = base + OFF_BLO + t*GB_STRIDE + n0 + g;
            unsigned bhi[2] = {Bh[0], Bh[4*GB_STRIDE]};
            unsigned blo[2] = {Bl[0], Bl[4*GB_STRIDE]};
            mma16(acc[0][j], ahi[0], bhi);
            mma16(acc[1][j], ahi[1], bhi);
            mma16(acc[0][j], ahi[0], blo);
            mma16(acc[1][j], ahi[1], blo);
            mma16(acc[0][j], alo[0], bhi);
            mma16(acc[1][j], alo[1], bhi);
        }
        if(nxt) stage(su + ((kt+1)&1)*BUFU);
        __syncthreads();
    }
    #pragma unroll
    for(int i=0;i<2;i++){
        int row = bm + wm + i*16 + g;
        #pragma unroll
        for(int j=0;j<8;j++){
            int col = bn + wn + j*8 + 2*t;
            float2* cp0 = (float2*)(C + (long)row*N + col);
            float2* cp1 = (float2*)(C + (long)(row+8)*N + col);
            if(RESID){
                float2 o0 = *cp0, o1 = *cp1;
                acc[i][j][0]+=o0.x; acc[i][j][1]+=o0.y;
                acc[i][j][2]+=o1.x; acc[i][j][3]+=o1.y;
            }
            *cp0 = make_float2(acc[i][j][0], acc[i][j][1]);
            *cp1 = make_float2(acc[i][j][2], acc[i][j][3]);
        }
    }
    if(LNEPI){
        int wc = w>>2;
        float rs1[4]={0.f,0.f,0.f,0.f}, rs2[4]={0.f,0.f,0.f,0.f};
        #pragma unroll
        for(int i=0;i<2;i++)
            #pragma unroll
            for(int j=0;j<8;j++){
                float e0=acc[i][j][0], e1=acc[i][j][1];
                float e2=acc[i][j][2], e3=acc[i][j][3];
                rs1[i*2  ] += e0+e1; rs2[i*2  ] += e0*e0+e1*e1;
                rs1[i*2+1] += e2+e3; rs2[i*2+1] += e2*e2+e3*e3;
            }
        #pragma unroll
        for(int o=1;o<4;o<<=1)
            #pragma unroll
            for(int q=0;q<4;q++){
                rs1[q]+=__shfl_xor_sync(~0u,rs1[q],o);
                rs2[q]+=__shfl_xor_sync(~0u,rs2[q],o);
            }
        if(t==0){
            #pragma unroll
            for(int q=0;q<4;q++){
                int lr = wm + (q>>1)*16 + g + (q&1)*8;
                spart[lr*4 + wc*2    ] = rs1[q];
                spart[lr*4 + wc*2 + 1] = rs2[q];
            }
        }
        __syncthreads();
        #pragma unroll
        for(int i=0;i<2;i++)
            #pragma unroll
            for(int half=0; half<2; half++){
                int lr = wm + i*16 + g + half*8;
                float S1 = spart[lr*4] + spart[lr*4+2];
                float S2 = spart[lr*4+1] + spart[lr*4+3];
                float mu = S1*(1.f/128.f);
                float r  = rsqrtf(S2*(1.f/128.f)-mu*mu + 1e-6f);
                long row = bm + lr;
                #pragma unroll
                for(int j=0;j<8;j++){
                    int col = wn + j*8 + 2*t;
                    float2 lw = *(const float2*)(lnw + col);
                    float e0 = (acc[i][j][half*2  ]-mu)*r*lw.x;
                    float e1 = (acc[i][j][half*2+1]-mu)*r*lw.y;
                    *(float2*)(g_ln + row*128 + col) = make_float2(e0,e1);
                }
            }
    }
}

// fused causal conv + SiLU + headwise q/k/v
__global__ void __launch_bounds__(256) k_convhead(const float* __restrict__ cw,
                                                  const float* __restrict__ cb,
                                                  const float* __restrict__ Wq,
                                                  const float* __restrict__ Wk,
                                                  const float* __restrict__ Wv){
    __shared__ float sup[19][256];
    __shared__ float sxc[16][256];
    int t0 = blockIdx.x<<4;
    int s0 = t0 & 255;
    int tid = threadIdx.x;
    #pragma unroll
    for(int i=0;i<19;i++){
        int s = s0 - 3 + i;
        sup[i][tid] = (s>=0) ? g_up[(long)(t0-3+i)*512 + tid] : 0.f;
    }
    __syncthreads();
    int c = tid;
    const float* w = cw + c*4;
    float w0=w[0],w1=w[1],w2=w[2],w3=w[3], bb=cb[c];
    #pragma unroll
    for(int t=0;t<16;t++){
        float acc = bb;
        acc = fmaf(sup[t  ][c], w0, acc);
        acc = fmaf(sup[t+1][c], w1, acc);
        acc = fmaf(sup[t+2][c], w2, acc);
        acc = fmaf(sup[t+3][c], w3, acc);
        float xcv = siluf(acc);
        sxc[t][c] = xcv;
        g_xc[(long)(t0+t)*256 + c] = xcv;
    }
    __syncthreads();
    int nb = c>>2, l = c&3;
    float wq[4], wk[4], wv[4];
    #pragma unroll
    for(int k=0;k<4;k++){
        wq[k]=Wq[nb*16+k*4+l]; wk[k]=Wk[nb*16+k*4+l]; wv[k]=Wv[nb*16+k*4+l];
    }
    #pragma unroll
    for(int t=0;t<16;t++){
        float aq=0.f, ak=0.f, av=0.f;
        #pragma unroll
        for(int k=0;k<4;k++){
            float xv = sxc[t][nb*4+k];
            float mv = sup[t+3][nb*4+k];
            aq=fmaf(xv,wq[k],aq); ak=fmaf(xv,wk[k],ak); av=fmaf(mv,wv[k],av);
        }
        g_q[(long)(t0+t)*256+c]=aq;
        g_k[(long)(t0+t)*256+c]=ak;
        g_v[(long)(t0+t)*256+c]=av;
    }
}

// gate projections: 2 tokens per warp, shared weight fetch
__global__ void __launch_bounds__(256) k_gatesproj(const float* __restrict__ Wig,
                                                   const float* __restrict__ big,
                                                   const float* __restrict__ Wfg,
                                                   const float* __restrict__ bfg){
    int warp = threadIdx.x>>5, lane = threadIdx.x&31;
    int t0 = blockIdx.x*16 + warp*2;
    const float* qp0 = g_q + (long)t0*256;
    const float* kp0 = g_k + (long)t0*256;
    const float* vp0 = g_v + (long)t0*256;
    float vA[24], vB[24];
    #pragma unroll
    for(int i=0;i<8;i++){ vA[i]    = qp0[lane+i*32]; vB[i]    = qp0[256+lane+i*32]; }
    #pragma unroll
    for(int i=0;i<8;i++){ vA[8+i]  = kp0[lane+i*32]; vB[8+i]  = kp0[256+lane+i*32]; }
    #pragma unroll
    for(int i=0;i<8;i++){ vA[16+i] = vp0[lane+i*32]; vB[16+i] = vp0[256+lane+i*32]; }
    float iA0=0,iA1=0,iA2=0,iA3=0, fA0=0,fA1=0,fA2=0,fA3=0;
    float iB0=0,iB1=0,iB2=0,iB3=0, fB0=0,fB1=0,fB2=0,fB3=0;
    #pragma unroll
    for(int i=0;i<24;i++){
        int c = i*32 + lane;
        float4 wi = *(const float4*)(Wig + c*4);
        float4 wf = *(const float4*)(Wfg + c*4);
        float a = vA[i], b = vB[i];
        iA0=fmaf(a,wi.x,iA0); iA1=fmaf(a,wi.y,iA1); iA2=fmaf(a,wi.z,iA2); iA3=fmaf(a,wi.w,iA3);
        fA0=fmaf(a,wf.x,fA0); fA1=fmaf(a,wf.y,fA1); fA2=fmaf(a,wf.z,fA2); fA3=fmaf(a,wf.w,fA3);
        iB0=fmaf(b,wi.x,iB0); iB1=fmaf(b,wi.y,iB1); iB2=fmaf(b,wi.z,iB2); iB3=fmaf(b,wi.w,iB3);
        fB0=fmaf(b,wf.x,fB0); fB1=fmaf(b,wf.y,fB1); fB2=fmaf(b,wf.z,fB2); fB3=fmaf(b,wf.w,fB3);
    }
    #pragma unroll
    for(int o=16;o;o>>=1){
        iA0+=__shfl_xor_sync(~0u,iA0,o); iA1+=__shfl_xor_sync(~0u,iA1,o);
        iA2+=__shfl_xor_sync(~0u,iA2,o); iA3+=__shfl_xor_sync(~0u,iA3,o);
        fA0+=__shfl_xor_sync(~0u,fA0,o); fA1+=__shfl_xor_sync(~0u,fA1,o);
        fA2+=__shfl_xor_sync(~0u,fA2,o); fA3+=__shfl_xor_sync(~0u,fA3,o);
        iB0+=__shfl_xor_sync(~0u,iB0,o); iB1+=__shfl_xor_sync(~0u,iB1,o);
        iB2+=__shfl_xor_sync(~0u,iB2,o); iB3+=__shfl_xor_sync(~0u,iB3,o);
        fB0+=__shfl_xor_sync(~0u,fB0,o); fB1+=__shfl_xor_sync(~0u,fB1,o);
        fB2+=__shfl_xor_sync(~0u,fB2,o); fB3+=__shfl_xor_sync(~0u,fB3,o);
    }
    if(lane==0){
        int b0 = t0>>8, s0_ = t0&255;
        int base = b0*1024 + s0_;
        g_ig[base     ] = iA0 + big[0];
        g_ig[base+256 ] = iA1 + big[1];
        g_ig[base+512 ] = iA2 + big[2];
        g_ig[base+768 ] = iA3 + big[3];
        g_fg[base     ] = fA0 + bfg[0];
        g_fg[base+256 ] = fA1 + bfg[1];
        g_fg[base+512 ] = fA2 + bfg[2];
        g_fg[base+768 ] = fA3 + bfg[3];
        int t1 = t0+1;
        int b1 = t1>>8, s1_ = t1&255;
        int base1 = b1*1024 + s1_;
        g_ig[base1     ] = iB0 + big[0];
        g_ig[base1+256 ] = iB1 + big[1];
        g_ig[base1+512 ] = iB2 + big[2];
        g_ig[base1+768 ] = iB3 + big[3];
        g_fg[base1     ] = fB0 + bfg[0];
        g_fg[base1+256 ] = fB1 + bfg[1];
        g_fg[base1+512 ] = fB2 + bfg[2];
        g_fg[base1+768 ] = fB3 + bfg[3];
    }
}

// attention (256 thr) + gate-scan + precomputed per-j exp + fused epilogue -> g_pre
#define ATTN_SMEM ((256*64*2 + 256*5)*4)
__global__ void __launch_bounds__(256,1) k_attn(const float* __restrict__ gnw,
                                                const float* __restrict__ skipw){
    extern __shared__ float sm[];
    float2* ks2 = (float2*)sm;
    float2* vs2 = (float2*)(sm + 16384);
    float*  scs = sm + 32768;
    float*  sig = sm + 33024;
    float*  smd = sm + 33280;
    float*  sfg = sm + 33536;
    float*  sej = sm + 33792;
    int b = blockIdx.x>>2, hd = blockIdx.x&3;
    int tid = threadIdx.x;
    for(int i=tid; i<256*16; i+=256){
        int r = i>>4, c = i&15;
        ((float4*)ks2)[i] = *(const float4*)(g_k + (long)(b*256+r)*256 + hd*64 + c*4);
        ((float4*)vs2)[i] = *(const float4*)(g_v + (long)(b*256+r)*256 + hd*64 + c*4);
    }
    {
        int base = b*1024 + hd*256;
        sig[tid] = g_ig[base+tid];
        sfg[tid] = g_fg[base+tid];
    }
    __syncthreads();
    if(tid < 32){
        int lane = tid;
        float carry = 0.f, cpm = -1e30f;
        for(int ch=0; ch<8; ch++){
            int s = ch*32 + lane;
            float f = sfg[s];
            float lf = (f >= 0.f) ? -log1pf(__expf(-f)) : f - log1pf(__expf(f));
            float sc = lf;
            #pragma unroll
            for(int o=1;o<32;o<<=1){ float v=__shfl_up_sync(~0u,sc,o); if(lane>=o) sc+=v; }
            float cs = carry + sc;
            float e = sig[s] - cs;
            float pm = e;
            #pragma unroll
            for(int o=1;o<32;o<<=1){ float v=__shfl_up_sync(~0u,pm,o); if(lane>=o) pm=fmaxf(pm,v); }
            pm = fmaxf(pm, cpm);
            scs[s] = cs;
            smd[s] = cs + pm;
            carry += __shfl_sync(~0u, sc, 31);
            cpm = fmaxf(cpm, __shfl_sync(~0u, pm, 31));
        }
    }
    __syncthreads();
    sej[tid] = __expf(sig[tid] - scs[tid]);   // per-j factor, row-independent
    __syncthreads();
    int w = tid>>5, lane = tid&31;
    int rb = (w<4) ? w : 11-w;
    int row = rb*32 + lane;
    float2 qv[32];
    #pragma unroll
    for(int d=0;d<32;d++) qv[d] = *(const float2*)(g_q + (long)(b*256+row)*256 + hd*64 + d*2);
    float2 acc[32];
    #pragma unroll
    for(int d=0;d<32;d++) acc[d] = make_float2(0.f,0.f);
    float ssum = 0.f;
    float mdi = smd[row];
    float rowc = 0.125f * __expf(scs[row] - mdi);   // per-row factor (<= ~e^0.5)
    int jmax = (rb+1)<<5;
    for(int j=0;j<jmax;j++){
        const float4* kr4 = (const float4*)(ks2 + j*32);
        float2 d0 = make_float2(0.f,0.f), d1 = d0, d2 = d0, d3 = d0;
        #pragma unroll
        for(int i=0;i<16;i+=2){
            float4 k0 = kr4[i], k1 = kr4[i+1];
            f2fma(d0, qv[2*i  ], make_float2(k0.x,k0.y));
            f2fma(d1, qv[2*i+1], make_float2(k0.z,k0.w));
            f2fma(d2, qv[2*i+2], make_float2(k1.x,k1.y));
            f2fma(d3, qv[2*i+3], make_float2(k1.z,k1.w));
        }
        float dot = (d0.x+d0.y)+(d1.x+d1.y)+((d2.x+d2.y)+(d3.x+d3.y));
        float wv = 0.f;
        if (j <= row){
            wv = rowc * dot * sej[j];
            ssum += wv;
        }
        float2 w2 = make_float2(wv, wv);
        const float4* vr4 = (const float4*)(vs2 + j*32);
        #pragma unroll
        for(int i=0;i<16;i++){
            float4 vvq = vr4[i];
            f2fma(acc[2*i  ], w2, make_float2(vvq.x,vvq.y));
            f2fma(acc[2*i+1], w2, make_float2(vvq.z,vvq.w));
        }
    }
    float inv = 1.f/(fmaxf(fabsf(ssum), __expf(-mdi)) + 1e-6f);
    float o64[64];
    float s1 = 0.f, s2 = 0.f;
    #pragma unroll
    for(int d=0;d<32;d++){
        float e0 = acc[d].x*inv, e1 = acc[d].y*inv;
        o64[2*d]=e0; o64[2*d+1]=e1;
        s1 += e0+e1; s2 += e0*e0+e1*e1;
    }
    float mu = s1*(1.f/64.f);
    float r  = rsqrtf(s2*(1.f/64.f)-mu*mu + 1e-6f);
    long tglob = (long)(b*256+row);
    const float2* zp  = (const float2*)(g_up + tglob*512 + 256 + hd*64);
    const float2* xcp = (const float2*)(g_xc + tglob*256 + hd*64);
    const float2* gw  = (const float2*)(gnw + hd*64);
    const float2* sw  = (const float2*)(skipw + hd*64);
    float2* outp = (float2*)(g_pre + tglob*256 + hd*64);
    #pragma unroll
    for(int d=0;d<32;d++){
        float2 z2 = zp[d], xc2 = xcp[d], g2 = gw[d], k2 = sw[d];
        float2 o;
        o.x = ((o64[2*d  ]-mu)*r*g2.x + k2.x*xc2.x) * siluf(z2.x);
        o.y = ((o64[2*d+1]-mu)*r*g2.y + k2.y*xc2.y) * siluf(z2.y);
        outp[d] = o;
    }
}

// fused sLSTM conv + gate-input projections. block = 64 tokens, 512 threads
#define GS_SMEM ((67*128 + 64*128)*4)
__global__ void __launch_bounds__(512) k_gatein_s(const float* __restrict__ cw,
                                                  const float* __restrict__ cb,
                                                  const float* __restrict__ Wg,
                                                  const float* __restrict__ bg){
    extern __shared__ float gs[];
    float* sln = gs;
    float* sxc = gs + 67*128;
    int tid = threadIdx.x;
    int t0 = blockIdx.x*64;
    int s0 = t0 & 255;
    for(int i=tid; i<67*128; i+=512){
        int rr2 = i>>7, cc2 = i&127;
        int s = s0 - 3 + rr2;
        sln[i] = (s>=0) ? g_ln[(long)(t0-3+rr2)*128 + cc2] : 0.f;
    }
    int n = tid>>7, rr = tid&127, l = rr>>2, g = rr&3;
    int gn = g*4+n;
    float wreg[32];
    #pragma unroll
    for(int k=0;k<32;k++) wreg[k] = Wg[gn*1024 + k*32 + l];
    float breg = bg[g*128 + n*32 + l];
    int src = (g>=2);
    __syncthreads();
    {
        int c = tid & 127;
        int tb = tid >> 7;
        float w0=cw[c*4],w1=cw[c*4+1],w2=cw[c*4+2],w3=cw[c*4+3], bb=cb[c];
        #pragma unroll
        for(int p=0;p<16;p++){
            int ti = tb*16 + p;
            float a2 = bb;
            a2 = fmaf(sln[(ti  )*128+c], w0, a2);
            a2 = fmaf(sln[(ti+1)*128+c], w1, a2);
            a2 = fmaf(sln[(ti+2)*128+c], w2, a2);
            a2 = fmaf(sln[(ti+3)*128+c], w3, a2);
            sxc[ti*128+c] = siluf(a2);
        }
    }
    __syncthreads();
    for(int ti=0; ti<64; ti++){
        const float* in = src ? &sln[(ti+3)*128 + n*32] : &sxc[ti*128 + n*32];
        float acc = breg;
        #pragma unroll
        for(int k=0;k<32;k++) acc = fmaf(in[k], wreg[k], acc);
        int t = t0 + ti;
        int b = t>>8, s = t&255;
        g_gate[(long)((s*64+b)*4+n)*128 + l*4 + g] = acc;
    }
}

// sLSTM recurrence: one warp per (b, head)
__global__ void __launch_bounds__(128) k_scan(const float* __restrict__ R){
    int warp = threadIdx.x>>5, l = threadIdx.x&31;
    int p = blockIdx.x*4 + warp;
    int b = p>>2, n = p&3;
    float Rr[4][32];
    #pragma unroll
    for(int g=0;g<4;g++)
        #pragma unroll
        for(int k=0;k<32;k++) Rr[g][k] = R[((g*4+n)*32+k)*32 + l];
    const float4* gp = (const float4*)g_gate;
    long base4 = (b*4+n)*32 + l;
    const long st4 = 64*4*32;
    float c=0.f, nst=0.f, m=0.f, hval=0.f;
    float* yout = g_ys + (long)b*256*128 + n*32 + l;
    float4 gv = gp[base4];
    for(int s=0;s<256;s++){
        float4 gnx = (s<255) ? gp[base4 + (long)(s+1)*st4] : gv;
        float a0=0.f,a1=0.f,b0=0.f,b1=0.f,c0=0.f,c1=0.f,d0=0.f,d1=0.f;
        #pragma unroll
        for(int k=0;k<32;k+=2){
            float h0 = __shfl_sync(~0u,hval,k);
            float h1 = __shfl_sync(~0u,hval,k+1);
            a0 = fmaf(h0, Rr[0][k], a0); a1 = fmaf(h1, Rr[0][k+1], a1);
            b0 = fmaf(h0, Rr[1][k], b0); b1 = fmaf(h1, Rr[1][k+1], b1);
            c0 = fmaf(h0, Rr[2][k], c0); c1 = fmaf(h1, Rr[2][k+1], c1);
            d0 = fmaf(h0, Rr[3][k], d0); d1 = fmaf(h1, Rr[3][k+1], d1);
        }
        float ir = gv.x + (a0+a1), fr = gv.y + (b0+b1);
        float zr = gv.z + (c0+c1), orr = gv.w + (d0+d1);
        float mn = fmaxf(fr + m, ir);
        float ii = __expf(ir - mn);
        float ff = __expf(fr + m - mn);
        float zt = ftanh(zr);
        float o  = 1.f/(1.f+__expf(-orr));
        c   = ff*c + ii*zt;
        nst = ff*nst + ii;
        hval = __fdividef(o*c, nst + 1e-8f);
        m = mn;
        yout[(long)s*128] = hval;
        gv = gnx;
    }
}

// fused sLSTM head-norm + residual add + row LayerNorm
__global__ void __launch_bounds__(128) k_epis_ln(const float* __restrict__ gnw,
                                                 const float* __restrict__ lnw){
    __shared__ float ps[4], pq[4];
    int t = blockIdx.x, c = threadIdx.x;
    int lane = c&31, warp = c>>5;
    float x = g_ys[(long)t*128+c];
    float s1=x, s2=x*x;
    #pragma unroll
    for(int o=16;o;o>>=1){ s1+=__shfl_xor_sync(~0u,s1,o); s2+=__shfl_xor_sync(~0u,s2,o); }
    float mu = s1*(1.f/32.f);
    float r  = rsqrtf(s2*(1.f/32.f)-mu*mu + 1e-6f);
    float hn = g_h[(long)t*128+c] + (x-mu)*r*gnw[c];
    g_h[(long)t*128+c] = hn;
    float a1=hn, a2=hn*hn;
    #pragma unroll
    for(int o=16;o;o>>=1){ a1+=__shfl_xor_sync(~0u,a1,o); a2+=__shfl_xor_sync(~0u,a2,o); }
    if(lane==0){ ps[warp]=a1; pq[warp]=a2; }
    __syncthreads();
    float S1 = (ps[0]+ps[1])+(ps[2]+ps[3]);
    float S2 = (pq[0]+pq[1])+(pq[2]+pq[3]);
    float mu2 = S1*(1.f/128.f);
    float r2  = rsqrtf(S2*(1.f/128.f)-mu2*mu2 + 1e-6f);
    g_ln[(long)t*128+c] = (hn-mu2)*r2*lnw[c];
}

__global__ void k_out(const float* __restrict__ Wout, const float* __restrict__ bout,
                      float* __restrict__ out){
    __shared__ float sm[3][4];
    int b = blockIdx.x, d = threadIdx.x;
    float v = g_ln[(long)(b*256+255)*128 + d];
    #pragma unroll
    for(int o=0;o<3;o++){
        float p = v*Wout[d*3+o];
        #pragma unroll
        for(int off=16;off;off>>=1) p += __shfl_xor_sync(~0u,p,off);
        if((d&31)==0) sm[o][d>>5]=p;
    }
    __syncthreads();
    if(d<3) out[b*3+d] = sm[d][0]+sm[d][1]+sm[d][2]+sm[d][3] + bout[d];
}

extern "C" void kernel_launch(void* const* d_in, const int* in_sizes, int n_in,
                              void* d_out, int out_size){
    const float* x      = (const float*)d_in[0];
    const float* W_emb  = (const float*)d_in[1];
    const float* b_emb  = (const float*)d_in[2];
    const float* m_ln_w = (const float*)d_in[3];
    const float* m_Wup  = (const float*)d_in[4];
    const float* m_cw   = (const float*)d_in[5];
    const float* m_cb   = (const float*)d_in[6];
    const float* m_Wq   = (const float*)d_in[7];
    const float* m_Wk   = (const float*)d_in[8];
    const float* m_Wv   = (const float*)d_in[9];
    const float* m_Wig  = (const float*)d_in[10];
    const float* m_big  = (const float*)d_in[11];
    const float* m_Wfg  = (const float*)d_in[12];
    const float* m_bfg  = (const float*)d_in[13];
    const float* m_gn_w = (const float*)d_in[14];
    const float* m_skip = (const float*)d_in[15];
    const float* m_Wdown= (const float*)d_in[16];
    const float* s_ln_w = (const float*)d_in[17];
    const float* s_cw   = (const float*)d_in[18];
    const float* s_cb   = (const float*)d_in[19];
    const float* s_Wg   = (const float*)d_in[20];
    const float* s_bg   = (const float*)d_in[21];
    const float* s_R    = (const float*)d_in[22];
    const float* s_gn_w = (const float*)d_in[23];
    const float* s_ln2_w= (const float*)d_in[24];
    const float* s_Wfu  = (const float*)d_in[25];
    const float* s_Wfd  = (const float*)d_in[26];
    const float* postw  = (const float*)d_in[27];
    const float* W_out  = (const float*)d_in[28];
    const float* b_out  = (const float*)d_in[29];

    cudaFuncSetAttribute(k_attn, cudaFuncAttributeMaxDynamicSharedMemorySize, ATTN_SMEM);
    cudaFuncSetAttribute(k_gatein_s, cudaFuncAttributeMaxDynamicSharedMemorySize, GS_SMEM);
    cudaFuncSetAttribute(k_gemm128<0,false,false>, cudaFuncAttributeMaxDynamicSharedMemorySize, GEMM_SMEM);
    cudaFuncSetAttribute(k_gemm128<0,true,true>,   cudaFuncAttributeMaxDynamicSharedMemorySize, GEMM_SMEM);
    cudaFuncSetAttribute(k_gemm128<1,true,true>,   cudaFuncAttributeMaxDynamicSharedMemorySize, GEMM_SMEM);

    float *hbuf, *lnb, *upb, *preb, *ffub;
    cudaGetSymbolAddress((void**)&hbuf, g_h);
    cudaGetSymbolAddress((void**)&lnb,  g_ln);
    cudaGetSymbolAddress((void**)&upb,  g_up);
    cudaGetSymbolAddress((void**)&preb, g_pre);
    cudaGetSymbolAddress((void**)&ffub, g_ffu);

    const float* nextw[6] = { s_ln_w, m_ln_w + 128, s_ln_w + 128,
                              m_ln_w + 2*128, m_ln_w + 3*128, postw };

    k_embed_ln<<<TK,128>>>(x, W_emb, b_emb, m_ln_w);

    const char* bt = "msmsmm";
    int mi=0, si=0;
    for(int bi=0; bi<6; bi++){
        if(bt[bi]=='m'){
            { dim3 g2(4, 128);
              k_gemm128<0,false,false><<<g2,256,GEMM_SMEM>>>(lnb, m_Wup + (long)mi*128*512, upb, 128, 512, nullptr); }
            k_convhead<<<TK/16,256>>>(m_cw + mi*1024, m_cb + mi*256,
                                      m_Wq + mi*1024, m_Wk + mi*1024, m_Wv + mi*1024);
            k_gatesproj<<<TK/16,256>>>(m_Wig + mi*3072, m_big + mi*4, m_Wfg + mi*3072, m_bfg + mi*4);
            k_attn<<<256,256,ATTN_SMEM>>>(m_gn_w + mi*256, m_skip + mi*256);
            { dim3 g2(1, 128);
              k_gemm128<0,true,true><<<g2,256,GEMM_SMEM>>>(preb, m_Wdown + (long)mi*256*128, hbuf, 256, 128, nextw[bi]); }
            mi++;
        } else {
            k_gatein_s<<<256,512,GS_SMEM>>>(s_cw + si*512, s_cb + si*128,
                                            s_Wg + si*16384, s_bg + si*512);
            k_scan<<<64,128>>>(s_R + si*16384);
            k_epis_ln<<<TK,128>>>(s_gn_w + si*128, s_ln2_w + si*128);
            { dim3 g2(3, 128);
              k_gemm128<0,false,false><<<g2,256,GEMM_SMEM>>>(lnb, s_Wfu + (long)si*128*384, ffub, 128, 384, nullptr); }
            { dim3 g2(1, 128);
              k_gemm128<1,true,true><<<g2,256,GEMM_SMEM>>>(ffub, s_Wfd + (long)si*192*128, hbuf, 192, 128, nextw[bi]); }
            si++;
        }
    }
    k_out<<<64,128>>>(W_out, b_out, (float*)d_out);
}